// round 1
// baseline (speedup 1.0000x reference)
#include <cuda_runtime.h>

#define N_NODES   100000
#define NUM_RELS  16
#define NUM_BASES 8
#define D         128
#define KDIM      1152   // NUM_BASES*D + D (basis-agg block + self block)

// ---------------- scratch (device globals; no runtime allocation) -------------
__device__ float g_A[(size_t)N_NODES * KDIM];   // [N, 1152] GEMM A operand
__device__ float g_W[KDIM * 128];               // [1152, 128] combined weight (zero-padded cols)
__device__ float g_h0[(size_t)N_NODES * D];
__device__ float g_h1[(size_t)N_NODES * D];
__device__ int   g_cnt[N_NODES];
__device__ int   g_off[N_NODES + 1];
__device__ int   g_cur[N_NODES];
__device__ int   g_csr[1600000];                // packed (type<<17)|src, grouped by dst

// ---------------- CSR build --------------------------------------------------
__global__ void k_zero_cnt() {
    int i = blockIdx.x * blockDim.x + threadIdx.x;
    if (i < N_NODES) g_cnt[i] = 0;
}

__global__ void k_count(const int* __restrict__ dst, int E) {
    int e = blockIdx.x * blockDim.x + threadIdx.x;
    if (e < E) atomicAdd(&g_cnt[dst[e]], 1);
}

__global__ void k_scan() {
    __shared__ int ssum[1024];
    const int chunk = (N_NODES + 1023) / 1024;  // 98
    int t = threadIdx.x;
    int b = t * chunk;
    int e = b + chunk; if (e > N_NODES) e = N_NODES;
    int s = 0;
    for (int i = b; i < e; ++i) s += g_cnt[i];
    ssum[t] = s;
    __syncthreads();
    for (int off = 1; off < 1024; off <<= 1) {
        int v = (t >= off) ? ssum[t - off] : 0;
        __syncthreads();
        ssum[t] += v;
        __syncthreads();
    }
    int run = (t == 0) ? 0 : ssum[t - 1];
    for (int i = b; i < e; ++i) {
        g_off[i] = run; g_cur[i] = run;
        run += g_cnt[i];
    }
    if (t == 0) g_off[N_NODES] = ssum[1023];
}

__global__ void k_scatter(const int* __restrict__ src, const int* __restrict__ dst,
                          const int* __restrict__ typ, int E) {
    int e = blockIdx.x * blockDim.x + threadIdx.x;
    if (e < E) {
        int p = atomicAdd(&g_cur[dst[e]], 1);
        g_csr[p] = (typ[e] << 17) | src[e];
    }
}

// ---------------- weight concat: g_W = [bases (8*128 rows) ; root (128 rows)] --
__global__ void k_make_w(const float* __restrict__ bases, const float* __restrict__ root, int dout) {
    int idx = blockIdx.x * blockDim.x + threadIdx.x;
    if (idx >= KDIM * 128) return;
    int k = idx >> 7, o = idx & 127;
    float v = 0.f;
    if (o < dout)
        v = (k < NUM_BASES * D) ? bases[k * dout + o]
                                : root[(k - NUM_BASES * D) * dout + o];
    g_W[idx] = v;
}

// ---------------- pull-aggregate: warp per dst node ---------------------------
// A[n, b*128+f] = sum_{e->n} comp[type_e,b]/deg(n,type_e) * hin[src_e, f]
// A[n, 1024+f]  = hin[n, f]
#define PULL_WARPS 8
__global__ void k_pull(const float* __restrict__ hin, const float* __restrict__ comp) {
    __shared__ int   s_cnt[PULL_WARPS][16];
    __shared__ float s_sc [PULL_WARPS][128];
    const int w = threadIdx.x >> 5, lane = threadIdx.x & 31;
    const int wg = blockIdx.x * PULL_WARPS + w;
    const int nwarps = gridDim.x * PULL_WARPS;

    for (int n = wg; n < N_NODES; n += nwarps) {
        const int off = g_off[n], end = g_off[n + 1];
        if (lane < 16) s_cnt[w][lane] = 0;
        __syncwarp();
        for (int e = off + lane; e < end; e += 32)
            atomicAdd(&s_cnt[w][g_csr[e] >> 17], 1);
        __syncwarp();
        // scaled composition coefficients: comp[r,b] * 1/deg(n,r)
        #pragma unroll
        for (int idx = lane; idx < 128; idx += 32) {
            int r = idx >> 3;
            int c = s_cnt[w][r];
            float inv = (c > 0) ? (1.0f / (float)c) : 0.0f;
            s_sc[w][idx] = comp[idx] * inv;
        }
        __syncwarp();

        float4 acc[NUM_BASES];
        #pragma unroll
        for (int b = 0; b < NUM_BASES; ++b) acc[b] = make_float4(0.f, 0.f, 0.f, 0.f);

        for (int e = off; e < end; ++e) {
            const int p   = g_csr[e];
            const int src = p & 131071;
            const int r   = p >> 17;
            const float4 xv = *reinterpret_cast<const float4*>(hin + (size_t)src * D + lane * 4);
            const float* cp = &s_sc[w][r * NUM_BASES];
            #pragma unroll
            for (int b = 0; b < NUM_BASES; ++b) {
                const float c = cp[b];
                acc[b].x += c * xv.x; acc[b].y += c * xv.y;
                acc[b].z += c * xv.z; acc[b].w += c * xv.w;
            }
        }
        float* Ar = g_A + (size_t)n * KDIM;
        #pragma unroll
        for (int b = 0; b < NUM_BASES; ++b)
            *reinterpret_cast<float4*>(Ar + b * D + lane * 4) = acc[b];
        const float4 hv = *reinterpret_cast<const float4*>(hin + (size_t)n * D + lane * 4);
        *reinterpret_cast<float4*>(Ar + NUM_BASES * D + lane * 4) = hv;
    }
}

// ---------------- SGEMM: out[M,Nout] = g_A[M,1152] @ g_W[1152,(pad128)] + bias --
template <int BN, int TN>
__global__ __launch_bounds__(256, 2) void k_sgemm(const float* __restrict__ bias,
                                                  float* __restrict__ out,
                                                  int Nout, int relu) {
    constexpr int BM = 128, BK = 8, TM = 8;
    constexpr int TPR = BN / 4;                 // float4 per B-tile row
    __shared__ __align__(16) float As[2][BK][BM];
    __shared__ __align__(16) float Bs[2][BK][BN];

    const int tid  = threadIdx.x;
    const int m0   = blockIdx.x * BM;
    const int tr   = tid / (BN / TN);
    const int tc   = tid % (BN / TN);
    const int arow = tid >> 1;
    const int ak   = (tid & 1) * 4;
    const int brow = tid / TPR;
    const int bcol = (tid % TPR) * 4;
    const bool bact = (tid < BK * TPR);

    float acc[TM][TN];
    #pragma unroll
    for (int i = 0; i < TM; ++i)
        #pragma unroll
        for (int j = 0; j < TN; ++j) acc[i][j] = 0.f;

    auto ldgA = [&](int kt) -> float4 {
        if (m0 + arow < N_NODES)
            return *reinterpret_cast<const float4*>(&g_A[(size_t)(m0 + arow) * KDIM + kt + ak]);
        return make_float4(0.f, 0.f, 0.f, 0.f);
    };
    auto ldgB = [&](int kt) -> float4 {
        if (bact)
            return *reinterpret_cast<const float4*>(&g_W[(kt + brow) * 128 + bcol]);
        return make_float4(0.f, 0.f, 0.f, 0.f);
    };
    auto sts = [&](int bf, float4 ra, float4 rb) {
        As[bf][ak + 0][arow] = ra.x;
        As[bf][ak + 1][arow] = ra.y;
        As[bf][ak + 2][arow] = ra.z;
        As[bf][ak + 3][arow] = ra.w;
        if (bact) *reinterpret_cast<float4*>(&Bs[bf][brow][bcol]) = rb;
    };
    auto compute_tile = [&](int bf) {
        #pragma unroll
        for (int k = 0; k < BK; ++k) {
            float a[TM];
            #pragma unroll
            for (int ii = 0; ii < TM; ii += 4) {
                float4 av = *reinterpret_cast<const float4*>(&As[bf][k][tr * TM + ii]);
                a[ii] = av.x; a[ii + 1] = av.y; a[ii + 2] = av.z; a[ii + 3] = av.w;
            }
            float b[TN];
            #pragma unroll
            for (int jj = 0; jj < TN; jj += 4) {
                float4 bv = *reinterpret_cast<const float4*>(&Bs[bf][k][tc * TN + jj]);
                b[jj] = bv.x; b[jj + 1] = bv.y; b[jj + 2] = bv.z; b[jj + 3] = bv.w;
            }
            #pragma unroll
            for (int i = 0; i < TM; ++i)
                #pragma unroll
                for (int j = 0; j < TN; ++j)
                    acc[i][j] += a[i] * b[j];
        }
    };

    float4 ra = ldgA(0), rb = ldgB(0);
    sts(0, ra, rb);
    __syncthreads();
    int buf = 0;
    for (int kt = BK; kt < KDIM; kt += BK) {
        ra = ldgA(kt); rb = ldgB(kt);
        compute_tile(buf);
        sts(buf ^ 1, ra, rb);
        __syncthreads();
        buf ^= 1;
    }
    compute_tile(buf);

    #pragma unroll
    for (int i = 0; i < TM; ++i) {
        int row = m0 + tr * TM + i;
        if (row < N_NODES) {
            #pragma unroll
            for (int j = 0; j < TN; ++j) {
                int col = tc * TN + j;
                if (col < Nout) {
                    float v = acc[i][j] + bias[col];
                    if (relu) v = fmaxf(v, 0.f);
                    out[(size_t)row * Nout + col] = v;
                }
            }
        }
    }
}

// ---------------- launch ------------------------------------------------------
extern "C" void kernel_launch(void* const* d_in, const int* in_sizes, int n_in,
                              void* d_out, int out_size) {
    const float* x      = (const float*)d_in[0];
    const int*   esrc   = (const int*)  d_in[1];
    const int*   edst   = (const int*)  d_in[2];
    const int*   etyp   = (const int*)  d_in[3];
    const float* bases0 = (const float*)d_in[4];
    const float* comp0  = (const float*)d_in[5];
    const float* root0  = (const float*)d_in[6];
    const float* bias0  = (const float*)d_in[7];
    const float* bases1 = (const float*)d_in[8];
    const float* comp1  = (const float*)d_in[9];
    const float* root1  = (const float*)d_in[10];
    const float* bias1  = (const float*)d_in[11];
    const float* bases2 = (const float*)d_in[12];
    const float* comp2  = (const float*)d_in[13];
    const float* root2  = (const float*)d_in[14];
    const float* bias2  = (const float*)d_in[15];
    float* out = (float*)d_out;
    const int E = in_sizes[1];

    void* p;
    cudaGetSymbolAddress(&p, g_h0); float* h0 = (float*)p;
    cudaGetSymbolAddress(&p, g_h1); float* h1 = (float*)p;

    // CSR by dst (reused by all 3 layers)
    k_zero_cnt<<<(N_NODES + 511) / 512, 512>>>();
    k_count  <<<(E + 255) / 256, 256>>>(edst, E);
    k_scan   <<<1, 1024>>>();
    k_scatter<<<(E + 255) / 256, 256>>>(esrc, edst, etyp, E);

    const int wgrid = (KDIM * 128 + 255) / 256;
    const int ggrid = (N_NODES + 127) / 128;

    // layer 0
    k_make_w<<<wgrid, 256>>>(bases0, root0, D);
    k_pull  <<<2048, 256>>>(x, comp0);
    k_sgemm<128, 8><<<ggrid, 256>>>(bias0, h0, D, 1);

    // layer 1
    k_make_w<<<wgrid, 256>>>(bases1, root1, D);
    k_pull  <<<2048, 256>>>(h0, comp1);
    k_sgemm<128, 8><<<ggrid, 256>>>(bias1, h1, D, 1);

    // layer 2 (d_out = 40, use BN=64 tile)
    k_make_w<<<wgrid, 256>>>(bases2, root2, 40);
    k_pull  <<<2048, 256>>>(h1, comp2);
    k_sgemm<64, 4><<<ggrid, 256>>>(bias2, out, 40, 0);
}

// round 2
// speedup vs baseline: 1.6763x; 1.6763x over previous
#include <cuda_runtime.h>
#include <cstdint>

#define N_NODES   100000
#define N_PAD     100096          // 782 * 128
#define NUM_RELS  16
#define NUM_BASES 8
#define D         128
#define KDIM      1152            // NUM_BASES*D + D

// ---------------- scratch (device globals; zero-initialized at load) ----------
__device__ float g_A[(size_t)N_PAD * KDIM];     // [Npad, 1152] tf32-rounded
__device__ float g_W[KDIM * 128];               // [1152, 128]  tf32-rounded, zero-pad cols
__device__ float g_h0[(size_t)N_PAD * D];
__device__ float g_h1[(size_t)N_PAD * D];
__device__ int   g_cnt[N_NODES];
__device__ int   g_off[N_NODES + 1];
__device__ int   g_cur[N_NODES];
__device__ int   g_csr[1600000];                // packed (type<<17)|src, grouped by dst

// ---------------- small helpers ----------------------------------------------
__device__ __forceinline__ float tf32r(float x) {
    float r;
    asm("cvt.rna.tf32.f32 %0, %1;" : "=f"(r) : "f"(x));
    return r;
}
__device__ __forceinline__ uint32_t s2u(const void* p) {
    return (uint32_t)__cvta_generic_to_shared(p);
}
__device__ __forceinline__ void cp16(uint32_t smem, const void* gmem) {
    asm volatile("cp.async.cg.shared.global [%0], [%1], 16;\n" :: "r"(smem), "l"(gmem));
}
#define CP_COMMIT() asm volatile("cp.async.commit_group;\n" ::: "memory")
#define CP_WAIT(N)  asm volatile("cp.async.wait_group %0;\n" :: "n"(N) : "memory")

__device__ __forceinline__ void mma_tf32(float4& c,
                                         uint32_t a0, uint32_t a1, uint32_t a2, uint32_t a3,
                                         uint32_t b0, uint32_t b1) {
    asm volatile(
        "mma.sync.aligned.m16n8k8.row.col.f32.tf32.tf32.f32 "
        "{%0,%1,%2,%3}, {%4,%5,%6,%7}, {%8,%9}, {%0,%1,%2,%3};\n"
        : "+f"(c.x), "+f"(c.y), "+f"(c.z), "+f"(c.w)
        : "r"(a0), "r"(a1), "r"(a2), "r"(a3), "r"(b0), "r"(b1));
}

// ---------------- CSR build --------------------------------------------------
__global__ void k_zero_cnt() {
    int i = blockIdx.x * blockDim.x + threadIdx.x;
    if (i < N_NODES) g_cnt[i] = 0;
}

__global__ void k_count(const int* __restrict__ dst, int E) {
    int e = blockIdx.x * blockDim.x + threadIdx.x;
    if (e < E) atomicAdd(&g_cnt[dst[e]], 1);
}

__global__ void k_scan() {
    __shared__ int ssum[1024];
    const int chunk = (N_NODES + 1023) / 1024;
    int t = threadIdx.x;
    int b = t * chunk;
    int e = b + chunk; if (e > N_NODES) e = N_NODES;
    int s = 0;
    for (int i = b; i < e; ++i) s += g_cnt[i];
    ssum[t] = s;
    __syncthreads();
    for (int off = 1; off < 1024; off <<= 1) {
        int v = (t >= off) ? ssum[t - off] : 0;
        __syncthreads();
        ssum[t] += v;
        __syncthreads();
    }
    int run = (t == 0) ? 0 : ssum[t - 1];
    for (int i = b; i < e; ++i) {
        g_off[i] = run; g_cur[i] = run;
        run += g_cnt[i];
    }
    if (t == 0) g_off[N_NODES] = ssum[1023];
}

__global__ void k_scatter(const int* __restrict__ src, const int* __restrict__ dst,
                          const int* __restrict__ typ, int E) {
    int e = blockIdx.x * blockDim.x + threadIdx.x;
    if (e < E) {
        int p = atomicAdd(&g_cur[dst[e]], 1);
        g_csr[p] = (typ[e] << 17) | src[e];
    }
}

// ---------------- weight concat (tf32-rounded) --------------------------------
__global__ void k_make_w(const float* __restrict__ bases, const float* __restrict__ root, int dout) {
    int idx = blockIdx.x * blockDim.x + threadIdx.x;
    if (idx >= KDIM * 128) return;
    int k = idx >> 7, o = idx & 127;
    float v = 0.f;
    if (o < dout)
        v = (k < NUM_BASES * D) ? bases[k * dout + o]
                                : root[(k - NUM_BASES * D) * dout + o];
    g_W[idx] = tf32r(v);
}

// ---------------- pull-aggregate: warp per dst node ---------------------------
#define PULL_WARPS 8
__global__ void k_pull(const float* __restrict__ hin, const float* __restrict__ comp) {
    __shared__ int   s_cnt[PULL_WARPS][16];
    __shared__ float s_sc [PULL_WARPS][128];
    const int w = threadIdx.x >> 5, lane = threadIdx.x & 31;
    const int wg = blockIdx.x * PULL_WARPS + w;
    const int nwarps = gridDim.x * PULL_WARPS;

    for (int n = wg; n < N_NODES; n += nwarps) {
        const int off = g_off[n], end = g_off[n + 1];
        if (lane < 16) s_cnt[w][lane] = 0;
        __syncwarp();
        for (int e = off + lane; e < end; e += 32)
            atomicAdd(&s_cnt[w][g_csr[e] >> 17], 1);
        __syncwarp();
        #pragma unroll
        for (int idx = lane; idx < 128; idx += 32) {
            int r = idx >> 3;
            int c = s_cnt[w][r];
            float inv = (c > 0) ? (1.0f / (float)c) : 0.0f;
            s_sc[w][idx] = comp[idx] * inv;
        }
        __syncwarp();

        float4 acc[NUM_BASES];
        #pragma unroll
        for (int b = 0; b < NUM_BASES; ++b) acc[b] = make_float4(0.f, 0.f, 0.f, 0.f);

        for (int e = off; e < end; ++e) {
            const int p   = g_csr[e];
            const int src = p & 131071;
            const int r   = p >> 17;
            const float4 xv = *reinterpret_cast<const float4*>(hin + (size_t)src * D + lane * 4);
            const float* cp = &s_sc[w][r * NUM_BASES];
            #pragma unroll
            for (int b = 0; b < NUM_BASES; ++b) {
                const float c = cp[b];
                acc[b].x += c * xv.x; acc[b].y += c * xv.y;
                acc[b].z += c * xv.z; acc[b].w += c * xv.w;
            }
        }
        float* Ar = g_A + (size_t)n * KDIM;
        #pragma unroll
        for (int b = 0; b < NUM_BASES; ++b) {
            float4 v = make_float4(tf32r(acc[b].x), tf32r(acc[b].y),
                                   tf32r(acc[b].z), tf32r(acc[b].w));
            *reinterpret_cast<float4*>(Ar + b * D + lane * 4) = v;
        }
        const float4 hv = *reinterpret_cast<const float4*>(hin + (size_t)n * D + lane * 4);
        float4 hr = make_float4(tf32r(hv.x), tf32r(hv.y), tf32r(hv.z), tf32r(hv.w));
        *reinterpret_cast<float4*>(Ar + NUM_BASES * D + lane * 4) = hr;
    }
}

// ---------------- tf32 tensor-core GEMM ---------------------------------------
// out[M, Nout] = g_A[Mpad, 1152] @ g_W[1152, 128] + bias (optionally relu)
// Block 128x128, BK=16, 8 warps (2 x 4), warp tile 64x32, 2-stage cp.async.
#define BMT 128
#define BNT 128
#define BKT 16
#define APAD 20
#define BPAD 132

__global__ __launch_bounds__(256, 2) void k_gemm_tc(const float* __restrict__ bias,
                                                    float* __restrict__ out,
                                                    int Nout, int relu, int predM) {
    __shared__ float As[2][BMT][APAD];
    __shared__ float Bs[2][BKT][BPAD];

    const int tid  = threadIdx.x;
    const int m0   = blockIdx.x * BMT;
    const int wid  = tid >> 5, lane = tid & 31;
    const int wm   = wid >> 2;          // 0..1
    const int wn   = wid & 3;           // 0..3
    const int g    = lane >> 2;         // 0..7
    const int t    = lane & 3;          // 0..3

    float4 c[4][4];
    #pragma unroll
    for (int i = 0; i < 4; ++i)
        #pragma unroll
        for (int j = 0; j < 4; ++j) c[i][j] = make_float4(0.f, 0.f, 0.f, 0.f);

    // per-thread load coords (2 float4 each for A and B per stage)
    const int af0_r  = tid >> 2,           af0_k = (tid & 3) * 4;
    const int af1_r  = (tid + 256) >> 2,   af1_k = (tid & 3) * 4;
    const int bf0_k  = tid >> 5,           bf0_n = (tid & 31) * 4;
    const int bf1_k  = (tid + 256) >> 5,   bf1_n = (tid & 31) * 4;

    auto load_tile = [&](int st, int kt) {
        cp16(s2u(&As[st][af0_r][af0_k]), &g_A[(size_t)(m0 + af0_r) * KDIM + kt + af0_k]);
        cp16(s2u(&As[st][af1_r][af1_k]), &g_A[(size_t)(m0 + af1_r) * KDIM + kt + af1_k]);
        cp16(s2u(&Bs[st][bf0_k][bf0_n]), &g_W[(kt + bf0_k) * 128 + bf0_n]);
        cp16(s2u(&Bs[st][bf1_k][bf1_n]), &g_W[(kt + bf1_k) * 128 + bf1_n]);
    };

    load_tile(0, 0);
    CP_COMMIT();

    const int nk = KDIM / BKT;          // 72
    int st = 0;
    for (int it = 0; it < nk; ++it) {
        if (it + 1 < nk) {
            load_tile(st ^ 1, (it + 1) * BKT);
            CP_COMMIT();
            CP_WAIT(1);
        } else {
            CP_WAIT(0);
        }
        __syncthreads();

        #pragma unroll
        for (int kk = 0; kk < BKT; kk += 8) {
            uint32_t a[4][4];
            #pragma unroll
            for (int i = 0; i < 4; ++i) {
                const int R = wm * 64 + i * 16;
                a[i][0] = __float_as_uint(As[st][R + g    ][kk + t    ]);
                a[i][1] = __float_as_uint(As[st][R + 8 + g][kk + t    ]);
                a[i][2] = __float_as_uint(As[st][R + g    ][kk + t + 4]);
                a[i][3] = __float_as_uint(As[st][R + 8 + g][kk + t + 4]);
            }
            uint32_t b[4][2];
            #pragma unroll
            for (int j = 0; j < 4; ++j) {
                const int C = wn * 32 + j * 8;
                b[j][0] = __float_as_uint(Bs[st][kk + t    ][C + g]);
                b[j][1] = __float_as_uint(Bs[st][kk + t + 4][C + g]);
            }
            #pragma unroll
            for (int i = 0; i < 4; ++i)
                #pragma unroll
                for (int j = 0; j < 4; ++j)
                    mma_tf32(c[i][j], a[i][0], a[i][1], a[i][2], a[i][3], b[j][0], b[j][1]);
        }
        __syncthreads();
        st ^= 1;
    }

    // epilogue
    #pragma unroll
    for (int i = 0; i < 4; ++i) {
        const int r0 = m0 + wm * 64 + i * 16 + g;
        #pragma unroll
        for (int j = 0; j < 4; ++j) {
            const int col = wn * 32 + j * 8 + 2 * t;
            if (col < Nout) {
                float b0 = bias[col];
                float b1 = (col + 1 < Nout) ? bias[col + 1] : 0.f;
                float v00 = c[i][j].x + b0, v01 = c[i][j].y + b1;
                float v10 = c[i][j].z + b0, v11 = c[i][j].w + b1;
                if (relu) {
                    v00 = fmaxf(v00, 0.f); v01 = fmaxf(v01, 0.f);
                    v10 = fmaxf(v10, 0.f); v11 = fmaxf(v11, 0.f);
                }
                const bool c1ok = (col + 1 < Nout);
                if (!predM || r0 < N_NODES) {
                    out[(size_t)r0 * Nout + col] = v00;
                    if (c1ok) out[(size_t)r0 * Nout + col + 1] = v01;
                }
                if (!predM || r0 + 8 < N_NODES) {
                    out[(size_t)(r0 + 8) * Nout + col] = v10;
                    if (c1ok) out[(size_t)(r0 + 8) * Nout + col + 1] = v11;
                }
            }
        }
    }
}

// ---------------- launch ------------------------------------------------------
extern "C" void kernel_launch(void* const* d_in, const int* in_sizes, int n_in,
                              void* d_out, int out_size) {
    const float* x      = (const float*)d_in[0];
    const int*   esrc   = (const int*)  d_in[1];
    const int*   edst   = (const int*)  d_in[2];
    const int*   etyp   = (const int*)  d_in[3];
    const float* bases0 = (const float*)d_in[4];
    const float* comp0  = (const float*)d_in[5];
    const float* root0  = (const float*)d_in[6];
    const float* bias0  = (const float*)d_in[7];
    const float* bases1 = (const float*)d_in[8];
    const float* comp1  = (const float*)d_in[9];
    const float* root1  = (const float*)d_in[10];
    const float* bias1  = (const float*)d_in[11];
    const float* bases2 = (const float*)d_in[12];
    const float* comp2  = (const float*)d_in[13];
    const float* root2  = (const float*)d_in[14];
    const float* bias2  = (const float*)d_in[15];
    float* out = (float*)d_out;
    const int E = in_sizes[1];

    void* p;
    cudaGetSymbolAddress(&p, g_h0); float* h0 = (float*)p;
    cudaGetSymbolAddress(&p, g_h1); float* h1 = (float*)p;

    // CSR by dst (reused by all 3 layers)
    k_zero_cnt<<<(N_NODES + 511) / 512, 512>>>();
    k_count  <<<(E + 255) / 256, 256>>>(edst, E);
    k_scan   <<<1, 1024>>>();
    k_scatter<<<(E + 255) / 256, 256>>>(esrc, edst, etyp, E);

    const int wgrid = (KDIM * 128 + 255) / 256;
    const int ggrid = N_PAD / BMT;   // 782

    // layer 0
    k_make_w<<<wgrid, 256>>>(bases0, root0, D);
    k_pull  <<<2048, 256>>>(x, comp0);
    k_gemm_tc<<<ggrid, 256>>>(bias0, h0, D, 1, 0);

    // layer 1
    k_make_w<<<wgrid, 256>>>(bases1, root1, D);
    k_pull  <<<2048, 256>>>(h0, comp1);
    k_gemm_tc<<<ggrid, 256>>>(bias1, h1, D, 1, 0);

    // layer 2 (d_out = 40)
    k_make_w<<<wgrid, 256>>>(bases2, root2, 40);
    k_pull  <<<2048, 256>>>(h1, comp2);
    k_gemm_tc<<<ggrid, 256>>>(bias2, out, 40, 0, 1);
}

// round 4
// speedup vs baseline: 2.4034x; 1.4338x over previous
#include <cuda_runtime.h>
#include <cuda_fp16.h>
#include <cstdint>

#define N_NODES   100000
#define N_PAD     100096          // 782 * 128
#define NUM_RELS  16
#define NUM_BASES 8
#define D         128
#define KDIM      1152            // NUM_BASES*D + D

// ---------------- scratch (device globals; zero-initialized at load) ----------
__device__ __half g_Ah[(size_t)N_PAD * KDIM];   // [Npad, 1152] fp16
__device__ __half g_Wf[128 * KDIM];             // transposed: [n][k] fp16, zero-pad rows
__device__ float g_h0[(size_t)N_PAD * D];
__device__ float g_h1[(size_t)N_PAD * D];
__device__ int   g_cnt[N_NODES];
__device__ int   g_off[N_NODES + 1];
__device__ int   g_cur[N_NODES];
__device__ int   g_csr[1600000];                // packed (type<<17)|src, grouped by dst

// ---------------- PTX helpers -------------------------------------------------
__device__ __forceinline__ uint32_t s2u(const void* p) {
    return (uint32_t)__cvta_generic_to_shared(p);
}
__device__ __forceinline__ void cp16(uint32_t smem, const void* gmem) {
    asm volatile("cp.async.cg.shared.global [%0], [%1], 16;\n" :: "r"(smem), "l"(gmem));
}
#define CP_COMMIT() asm volatile("cp.async.commit_group;\n" ::: "memory")
#define CP_WAIT(N)  asm volatile("cp.async.wait_group %0;\n" :: "n"(N) : "memory")

__device__ __forceinline__ void mma_f16(float4& c,
                                        uint32_t a0, uint32_t a1, uint32_t a2, uint32_t a3,
                                        uint32_t b0, uint32_t b1) {
    asm volatile(
        "mma.sync.aligned.m16n8k16.row.col.f32.f16.f16.f32 "
        "{%0,%1,%2,%3}, {%4,%5,%6,%7}, {%8,%9}, {%0,%1,%2,%3};\n"
        : "+f"(c.x), "+f"(c.y), "+f"(c.z), "+f"(c.w)
        : "r"(a0), "r"(a1), "r"(a2), "r"(a3), "r"(b0), "r"(b1));
}

// ---------------- CSR build --------------------------------------------------
__global__ void k_zero_cnt() {
    int i = blockIdx.x * blockDim.x + threadIdx.x;
    if (i < N_NODES) g_cnt[i] = 0;
}
__global__ void k_count(const int* __restrict__ dst, int E) {
    int e = blockIdx.x * blockDim.x + threadIdx.x;
    if (e < E) atomicAdd(&g_cnt[dst[e]], 1);
}
__global__ void k_scan() {
    __shared__ int ssum[1024];
    const int chunk = (N_NODES + 1023) / 1024;
    int t = threadIdx.x;
    int b = t * chunk;
    int e = b + chunk; if (e > N_NODES) e = N_NODES;
    int s = 0;
    for (int i = b; i < e; ++i) s += g_cnt[i];
    ssum[t] = s;
    __syncthreads();
    for (int off = 1; off < 1024; off <<= 1) {
        int v = (t >= off) ? ssum[t - off] : 0;
        __syncthreads();
        ssum[t] += v;
        __syncthreads();
    }
    int run = (t == 0) ? 0 : ssum[t - 1];
    for (int i = b; i < e; ++i) {
        g_off[i] = run; g_cur[i] = run;
        run += g_cnt[i];
    }
    if (t == 0) g_off[N_NODES] = ssum[1023];
}
__global__ void k_scatter(const int* __restrict__ src, const int* __restrict__ dst,
                          const int* __restrict__ typ, int E) {
    int e = blockIdx.x * blockDim.x + threadIdx.x;
    if (e < E) {
        int p = atomicAdd(&g_cur[dst[e]], 1);
        g_csr[p] = (typ[e] << 17) | src[e];
    }
}

// ---------------- weight: transpose to [n][k], fp16 ---------------------------
__global__ void k_make_w(const float* __restrict__ bases, const float* __restrict__ root, int dout) {
    int idx = blockIdx.x * blockDim.x + threadIdx.x;
    if (idx >= 128 * KDIM) return;
    int n = idx / KDIM, k = idx % KDIM;
    float v = 0.f;
    if (n < dout)
        v = (k < NUM_BASES * D) ? bases[k * dout + n]
                                : root[(k - NUM_BASES * D) * dout + n];
    g_Wf[idx] = __float2half_rn(v);
}

// ---------------- pull-aggregate: warp per dst node ---------------------------
__device__ __forceinline__ void st_h4(__half* p, float4 v) {
    __half2 lo = __floats2half2_rn(v.x, v.y);
    __half2 hi = __floats2half2_rn(v.z, v.w);
    uint2 u;
    u.x = *reinterpret_cast<uint32_t*>(&lo);
    u.y = *reinterpret_cast<uint32_t*>(&hi);
    *reinterpret_cast<uint2*>(p) = u;
}

#define PULL_WARPS 8
__global__ void k_pull(const float* __restrict__ hin, const float* __restrict__ comp) {
    __shared__ int   s_cnt[PULL_WARPS][16];
    __shared__ float s_sc [PULL_WARPS][128];
    const int w = threadIdx.x >> 5, lane = threadIdx.x & 31;
    const int wg = blockIdx.x * PULL_WARPS + w;
    const int nwarps = gridDim.x * PULL_WARPS;

    for (int n = wg; n < N_NODES; n += nwarps) {
        const int off = g_off[n], end = g_off[n + 1];
        if (lane < 16) s_cnt[w][lane] = 0;
        __syncwarp();
        for (int e = off + lane; e < end; e += 32)
            atomicAdd(&s_cnt[w][g_csr[e] >> 17], 1);
        __syncwarp();
        #pragma unroll
        for (int idx = lane; idx < 128; idx += 32) {
            int r = idx >> 3;
            int c = s_cnt[w][r];
            float inv = (c > 0) ? (1.0f / (float)c) : 0.0f;
            s_sc[w][idx] = comp[idx] * inv;
        }
        __syncwarp();

        float4 acc[NUM_BASES];
        #pragma unroll
        for (int b = 0; b < NUM_BASES; ++b) acc[b] = make_float4(0.f, 0.f, 0.f, 0.f);

        for (int e = off; e < end; ++e) {
            const int p   = g_csr[e];
            const int src = p & 131071;
            const int r   = p >> 17;
            const float4 xv = *reinterpret_cast<const float4*>(hin + (size_t)src * D + lane * 4);
            const float* cp = &s_sc[w][r * NUM_BASES];
            #pragma unroll
            for (int b = 0; b < NUM_BASES; ++b) {
                const float c = cp[b];
                acc[b].x += c * xv.x; acc[b].y += c * xv.y;
                acc[b].z += c * xv.z; acc[b].w += c * xv.w;
            }
        }
        __half* Ar = g_Ah + (size_t)n * KDIM + lane * 4;
        #pragma unroll
        for (int b = 0; b < NUM_BASES; ++b)
            st_h4(Ar + b * D, acc[b]);
        const float4 hv = *reinterpret_cast<const float4*>(hin + (size_t)n * D + lane * 4);
        st_h4(Ar + NUM_BASES * D, hv);
    }
}

// ---------------- fp16 tensor-core GEMM ---------------------------------------
// out[M,Nout] = g_Ah[Mpad,1152] @ g_Wf^T + bias (optionally relu)
// Block 128xBN, BK=32, 8 warps (2 x 4), warp tile 64 x (BN/4), 3-stage cp.async.
template <int BN>
__global__ __launch_bounds__(256, 2) void k_gemm(const float* __restrict__ bias,
                                                 float* __restrict__ out,
                                                 int Nout, int relu, int predM) {
    constexpr int BK   = 32;
    constexpr int ROWB = (BK + 8) * 2;              // 80 bytes per smem row
    constexpr int JT   = BN / 32;                   // n8 tiles per warp
    constexpr int STAGE = (128 + BN) * ROWB;        // bytes per pipeline stage
    constexpr int NK   = KDIM / BK;                 // 36
    extern __shared__ char sm[];

    const int tid = threadIdx.x, wid = tid >> 5, lane = tid & 31;
    const int wm = wid >> 2, wn = wid & 3;
    const int g = lane >> 2, t = lane & 3;
    const int m0 = blockIdx.x * 128;
    const uint32_t smb = s2u(sm);

    float4 c[4][JT];
    #pragma unroll
    for (int i = 0; i < 4; ++i)
        #pragma unroll
        for (int j = 0; j < JT; ++j) c[i][j] = make_float4(0.f, 0.f, 0.f, 0.f);

    auto load_stage = [&](int st, int kt) {
        const uint32_t base = smb + st * STAGE;
        #pragma unroll
        for (int i = 0; i < 2; ++i) {                       // A: 512 chunks of 16B
            const int task = tid + i * 256;
            const int row = task >> 2, ch = task & 3;
            cp16(base + row * ROWB + ch * 16,
                 g_Ah + (size_t)(m0 + row) * KDIM + kt + ch * 8);
        }
        #pragma unroll
        for (int i = 0; i < (BN * 4) / 256; ++i) {          // B: BN*4 chunks
            const int task = tid + i * 256;
            const int row = task >> 2, ch = task & 3;
            cp16(base + 128 * ROWB + row * ROWB + ch * 16,
                 g_Wf + (size_t)row * KDIM + kt + ch * 8);
        }
        CP_COMMIT();
    };

    load_stage(0, 0);
    load_stage(1, BK);

    for (int it = 0; it < NK; ++it) {
        if (it < NK - 1) { CP_WAIT(1); } else { CP_WAIT(0); }
        __syncthreads();
        if (it + 2 < NK) load_stage((it + 2) % 3, (it + 2) * BK);

        const char* As = sm + (it % 3) * STAGE;
        const char* Bs = As + 128 * ROWB;
        #pragma unroll
        for (int kk = 0; kk < BK; kk += 16) {
            uint32_t a[4][4];
            #pragma unroll
            for (int i = 0; i < 4; ++i) {
                const int R = wm * 64 + i * 16;
                a[i][0] = *reinterpret_cast<const uint32_t*>(As + (R + g)     * ROWB + (kk + 2 * t)     * 2);
                a[i][1] = *reinterpret_cast<const uint32_t*>(As + (R + 8 + g) * ROWB + (kk + 2 * t)     * 2);
                a[i][2] = *reinterpret_cast<const uint32_t*>(As + (R + g)     * ROWB + (kk + 2 * t + 8) * 2);
                a[i][3] = *reinterpret_cast<const uint32_t*>(As + (R + 8 + g) * ROWB + (kk + 2 * t + 8) * 2);
            }
            uint32_t b[JT][2];
            #pragma unroll
            for (int j = 0; j < JT; ++j) {
                const int C = wn * (JT * 8) + j * 8;
                b[j][0] = *reinterpret_cast<const uint32_t*>(Bs + (C + g) * ROWB + (kk + 2 * t)     * 2);
                b[j][1] = *reinterpret_cast<const uint32_t*>(Bs + (C + g) * ROWB + (kk + 2 * t + 8) * 2);
            }
            #pragma unroll
            for (int i = 0; i < 4; ++i)
                #pragma unroll
                for (int j = 0; j < JT; ++j)
                    mma_f16(c[i][j], a[i][0], a[i][1], a[i][2], a[i][3], b[j][0], b[j][1]);
        }
    }

    // epilogue
    #pragma unroll
    for (int i = 0; i < 4; ++i) {
        const int r0 = m0 + wm * 64 + i * 16 + g;
        #pragma unroll
        for (int j = 0; j < JT; ++j) {
            const int col = wn * (JT * 8) + j * 8 + 2 * t;
            if (col < Nout) {
                float b0 = bias[col];
                float b1 = (col + 1 < Nout) ? bias[col + 1] : 0.f;
                float v00 = c[i][j].x + b0, v01 = c[i][j].y + b1;
                float v10 = c[i][j].z + b0, v11 = c[i][j].w + b1;
                if (relu) {
                    v00 = fmaxf(v00, 0.f); v01 = fmaxf(v01, 0.f);
                    v10 = fmaxf(v10, 0.f); v11 = fmaxf(v11, 0.f);
                }
                const bool c1ok = (col + 1 < Nout);
                if (!predM || r0 < N_NODES) {
                    out[(size_t)r0 * Nout + col] = v00;
                    if (c1ok) out[(size_t)r0 * Nout + col + 1] = v01;
                }
                if (!predM || r0 + 8 < N_NODES) {
                    out[(size_t)(r0 + 8) * Nout + col] = v10;
                    if (c1ok) out[(size_t)(r0 + 8) * Nout + col + 1] = v11;
                }
            }
        }
    }
}

// ---------------- launch ------------------------------------------------------
extern "C" void kernel_launch(void* const* d_in, const int* in_sizes, int n_in,
                              void* d_out, int out_size) {
    const float* x      = (const float*)d_in[0];
    const int*   esrc   = (const int*)  d_in[1];
    const int*   edst   = (const int*)  d_in[2];
    const int*   etyp   = (const int*)  d_in[3];
    const float* bases0 = (const float*)d_in[4];
    const float* comp0  = (const float*)d_in[5];
    const float* root0  = (const float*)d_in[6];
    const float* bias0  = (const float*)d_in[7];
    const float* bases1 = (const float*)d_in[8];
    const float* comp1  = (const float*)d_in[9];
    const float* root1  = (const float*)d_in[10];
    const float* bias1  = (const float*)d_in[11];
    const float* bases2 = (const float*)d_in[12];
    const float* comp2  = (const float*)d_in[13];
    const float* root2  = (const float*)d_in[14];
    const float* bias2  = (const float*)d_in[15];
    float* out = (float*)d_out;
    const int E = in_sizes[1];

    void* p;
    cudaGetSymbolAddress(&p, g_h0); float* h0 = (float*)p;
    cudaGetSymbolAddress(&p, g_h1); float* h1 = (float*)p;

    const int smem128 = 3 * (128 + 128) * 80;   // 61440
    const int smem64  = 3 * (128 + 64) * 80;    // 46080
    cudaFuncSetAttribute(k_gemm<128>, cudaFuncAttributeMaxDynamicSharedMemorySize, smem128);
    cudaFuncSetAttribute(k_gemm<64>,  cudaFuncAttributeMaxDynamicSharedMemorySize, smem64);

    // CSR by dst (reused by all 3 layers)
    k_zero_cnt<<<(N_NODES + 511) / 512, 512>>>();
    k_count  <<<(E + 255) / 256, 256>>>(edst, E);
    k_scan   <<<1, 1024>>>();
    k_scatter<<<(E + 255) / 256, 256>>>(esrc, edst, etyp, E);

    const int wgrid = (128 * KDIM + 255) / 256;   // 576
    const int ggrid = N_PAD / 128;                // 782

    // layer 0
    k_make_w<<<wgrid, 256>>>(bases0, root0, D);
    k_pull  <<<2048, 256>>>(x, comp0);
    k_gemm<128><<<ggrid, 256, smem128>>>(bias0, h0, D, 1, 0);

    // layer 1
    k_make_w<<<wgrid, 256>>>(bases1, root1, D);
    k_pull  <<<2048, 256>>>(h0, comp1);
    k_gemm<128><<<ggrid, 256, smem128>>>(bias1, h1, D, 1, 0);

    // layer 2 (d_out = 40)
    k_make_w<<<wgrid, 256>>>(bases2, root2, 40);
    k_pull  <<<2048, 256>>>(h1, comp2);
    k_gemm<64><<<ggrid, 256, smem64>>>(bias2, out, 40, 0, 1);
}

// round 5
// speedup vs baseline: 2.8295x; 1.1773x over previous
#include <cuda_runtime.h>
#include <cuda_fp16.h>
#include <cstdint>

#define N_NODES   100000
#define N_PAD     100096          // 782 * 128
#define NUM_RELS  16
#define NUM_BASES 8
#define D         128
#define KDIM      1152            // NUM_BASES*D + D

// ---------------- scratch (device globals; zero-initialized at load) ----------
__device__ __half g_Ah[(size_t)N_PAD * KDIM];   // [Npad, 1152] fp16 GEMM A
__device__ __half g_Wf[128 * KDIM];             // transposed: [n][k] fp16, zero-pad rows
__device__ __half g_hx[(size_t)N_NODES * D];    // fp16 copy of input x
__device__ __half g_h0[(size_t)N_PAD * D];      // fp16 hidden
__device__ __half g_h1[(size_t)N_PAD * D];
__device__ int   g_cnt[N_NODES];
__device__ int   g_off[N_NODES + 1];
__device__ int   g_cur[N_NODES];
__device__ int   g_csr[1600000];                // packed (type<<17)|src, grouped by dst

// ---------------- PTX helpers -------------------------------------------------
__device__ __forceinline__ uint32_t s2u(const void* p) {
    return (uint32_t)__cvta_generic_to_shared(p);
}
__device__ __forceinline__ void cp16(uint32_t smem, const void* gmem) {
    asm volatile("cp.async.cg.shared.global [%0], [%1], 16;\n" :: "r"(smem), "l"(gmem));
}
#define CP_COMMIT() asm volatile("cp.async.commit_group;\n" ::: "memory")
#define CP_WAIT(N)  asm volatile("cp.async.wait_group %0;\n" :: "n"(N) : "memory")

__device__ __forceinline__ void ffma2(uint64_t& d, uint64_t a, uint64_t b) {
    asm("fma.rn.f32x2 %0, %1, %2, %0;" : "+l"(d) : "l"(a), "l"(b));
}
__device__ __forceinline__ uint64_t pack_f2(float lo, float hi) {
    uint64_t r;
    asm("mov.b64 %0, {%1, %2};" : "=l"(r) : "f"(lo), "f"(hi));
    return r;
}
__device__ __forceinline__ float2 unpack_f2(uint64_t v) {
    float2 r;
    asm("mov.b64 {%0, %1}, %2;" : "=f"(r.x), "=f"(r.y) : "l"(v));
    return r;
}
__device__ __forceinline__ void ldsm4(uint32_t& r0, uint32_t& r1, uint32_t& r2, uint32_t& r3,
                                      uint32_t addr) {
    asm volatile("ldmatrix.sync.aligned.m8n8.x4.shared.b16 {%0,%1,%2,%3}, [%4];"
                 : "=r"(r0), "=r"(r1), "=r"(r2), "=r"(r3) : "r"(addr));
}
__device__ __forceinline__ void mma_f16(float4& c,
                                        uint32_t a0, uint32_t a1, uint32_t a2, uint32_t a3,
                                        uint32_t b0, uint32_t b1) {
    asm volatile(
        "mma.sync.aligned.m16n8k16.row.col.f32.f16.f16.f32 "
        "{%0,%1,%2,%3}, {%4,%5,%6,%7}, {%8,%9}, {%0,%1,%2,%3};\n"
        : "+f"(c.x), "+f"(c.y), "+f"(c.z), "+f"(c.w)
        : "r"(a0), "r"(a1), "r"(a2), "r"(a3), "r"(b0), "r"(b1));
}

// ---------------- CSR build --------------------------------------------------
__global__ void k_zero_cnt() {
    int i = blockIdx.x * blockDim.x + threadIdx.x;
    if (i < N_NODES) g_cnt[i] = 0;
}
__global__ void k_count(const int* __restrict__ dst, int E) {
    int e = blockIdx.x * blockDim.x + threadIdx.x;
    if (e < E) atomicAdd(&g_cnt[dst[e]], 1);
}
__global__ void k_scan() {
    __shared__ int ssum[1024];
    const int chunk = (N_NODES + 1023) / 1024;
    int t = threadIdx.x;
    int b = t * chunk;
    int e = b + chunk; if (e > N_NODES) e = N_NODES;
    int s = 0;
    for (int i = b; i < e; ++i) s += g_cnt[i];
    ssum[t] = s;
    __syncthreads();
    for (int off = 1; off < 1024; off <<= 1) {
        int v = (t >= off) ? ssum[t - off] : 0;
        __syncthreads();
        ssum[t] += v;
        __syncthreads();
    }
    int run = (t == 0) ? 0 : ssum[t - 1];
    for (int i = b; i < e; ++i) {
        g_off[i] = run; g_cur[i] = run;
        run += g_cnt[i];
    }
    if (t == 0) g_off[N_NODES] = ssum[1023];
}
__global__ void k_scatter(const int* __restrict__ src, const int* __restrict__ dst,
                          const int* __restrict__ typ, int E) {
    int e = blockIdx.x * blockDim.x + threadIdx.x;
    if (e < E) {
        int p = atomicAdd(&g_cur[dst[e]], 1);
        g_csr[p] = (typ[e] << 17) | src[e];
    }
}

// ---------------- x -> fp16 ---------------------------------------------------
__global__ void k_x2h(const float* __restrict__ x) {
    int i = blockIdx.x * blockDim.x + threadIdx.x;
    if (i < N_NODES * (D / 2)) {
        float2 v = reinterpret_cast<const float2*>(x)[i];
        reinterpret_cast<__half2*>(g_hx)[i] = __floats2half2_rn(v.x, v.y);
    }
}

// ---------------- weight: transpose to [n][k], fp16 ---------------------------
__global__ void k_make_w(const float* __restrict__ bases, const float* __restrict__ root, int dout) {
    int idx = blockIdx.x * blockDim.x + threadIdx.x;
    if (idx >= 128 * KDIM) return;
    int n = idx / KDIM, k = idx % KDIM;
    float v = 0.f;
    if (n < dout)
        v = (k < NUM_BASES * D) ? bases[k * dout + n]
                                : root[(k - NUM_BASES * D) * dout + n];
    g_Wf[idx] = __float2half_rn(v);
}

// ---------------- pull-aggregate: warp per dst node ---------------------------
#define PULL_WARPS 8
__global__ void k_pull(const __half* __restrict__ hin, const float* __restrict__ comp) {
    __shared__ int s_cnt[PULL_WARPS][16];
    __shared__ __align__(16) float2 s_sc[PULL_WARPS][16][8];  // (c,c) duplicated
    const int w = threadIdx.x >> 5, lane = threadIdx.x & 31;
    const int wg = blockIdx.x * PULL_WARPS + w;
    const int nwarps = gridDim.x * PULL_WARPS;

    for (int n = wg; n < N_NODES; n += nwarps) {
        const int off = g_off[n], end = g_off[n + 1];
        if (lane < 16) s_cnt[w][lane] = 0;
        __syncwarp();
        for (int e = off + lane; e < end; e += 32)
            atomicAdd(&s_cnt[w][g_csr[e] >> 17], 1);
        __syncwarp();
        #pragma unroll
        for (int idx = lane; idx < 128; idx += 32) {
            int r = idx >> 3, b = idx & 7;
            int c = s_cnt[w][r];
            float inv = (c > 0) ? (1.0f / (float)c) : 0.0f;
            float cc = comp[idx] * inv;
            s_sc[w][r][b] = make_float2(cc, cc);
        }
        __syncwarp();

        uint64_t acc[NUM_BASES][2];
        #pragma unroll
        for (int b = 0; b < NUM_BASES; ++b) { acc[b][0] = 0ull; acc[b][1] = 0ull; }

        for (int e = off; e < end; ++e) {
            const int p   = g_csr[e];
            const int src = p & 131071;
            const int r   = p >> 17;
            const uint2 hv = *reinterpret_cast<const uint2*>(hin + (size_t)src * D + lane * 4);
            float2 f0 = __half22float2(*reinterpret_cast<const __half2*>(&hv.x));
            float2 f1 = __half22float2(*reinterpret_cast<const __half2*>(&hv.y));
            const uint64_t x0 = pack_f2(f0.x, f0.y);
            const uint64_t x1 = pack_f2(f1.x, f1.y);
            const ulonglong2* cp = reinterpret_cast<const ulonglong2*>(&s_sc[w][r][0]);
            #pragma unroll
            for (int q = 0; q < 4; ++q) {
                const ulonglong2 c2 = cp[q];   // broadcast LDS.128
                ffma2(acc[2 * q][0],     x0, c2.x);
                ffma2(acc[2 * q][1],     x1, c2.x);
                ffma2(acc[2 * q + 1][0], x0, c2.y);
                ffma2(acc[2 * q + 1][1], x1, c2.y);
            }
        }
        __half* Ar = g_Ah + (size_t)n * KDIM + lane * 4;
        #pragma unroll
        for (int b = 0; b < NUM_BASES; ++b) {
            float2 lo = unpack_f2(acc[b][0]);
            float2 hi = unpack_f2(acc[b][1]);
            __half2 o0 = __floats2half2_rn(lo.x, lo.y);
            __half2 o1 = __floats2half2_rn(hi.x, hi.y);
            uint2 u;
            u.x = *reinterpret_cast<uint32_t*>(&o0);
            u.y = *reinterpret_cast<uint32_t*>(&o1);
            *reinterpret_cast<uint2*>(Ar + b * D) = u;
        }
        const uint2 sv = *reinterpret_cast<const uint2*>(hin + (size_t)n * D + lane * 4);
        *reinterpret_cast<uint2*>(Ar + NUM_BASES * D) = sv;
    }
}

// ---------------- fp16 tensor-core GEMM (ldmatrix + 3-stage cp.async) ---------
template <int BN, int HALF_OUT>
__global__ __launch_bounds__(256, 2) void k_gemm(const float* __restrict__ bias,
                                                 void* __restrict__ outp,
                                                 int Nout, int relu, int predM) {
    constexpr int BK   = 32;
    constexpr int ROWB = (BK + 8) * 2;              // 80 bytes per smem row
    constexpr int JT   = BN / 32;                   // n8 tiles per warp
    constexpr int STAGE = (128 + BN) * ROWB;        // bytes per pipeline stage
    constexpr int NK   = KDIM / BK;                 // 36
    extern __shared__ char sm[];

    const int tid = threadIdx.x, wid = tid >> 5, lane = tid & 31;
    const int wm = wid >> 2, wn = wid & 3;
    const int g = lane >> 2, t = lane & 3;
    const int m0 = blockIdx.x * 128;
    const uint32_t smb = s2u(sm);

    // ldmatrix per-thread base offsets
    const uint32_t a_base = (uint32_t)((wm * 64 + (lane & 15)) * ROWB + (lane >> 4) * 16);
    const uint32_t b_base = (uint32_t)((wn * (JT * 8) + ((lane >> 4) & 1) * 8 + (lane & 7)) * ROWB
                                       + ((lane >> 3) & 1) * 16);

    float4 c[4][JT];
    #pragma unroll
    for (int i = 0; i < 4; ++i)
        #pragma unroll
        for (int j = 0; j < JT; ++j) c[i][j] = make_float4(0.f, 0.f, 0.f, 0.f);

    auto load_stage = [&](int st, int kt) {
        const uint32_t base = smb + st * STAGE;
        #pragma unroll
        for (int i = 0; i < 2; ++i) {                       // A: 512 chunks of 16B
            const int task = tid + i * 256;
            const int row = task >> 2, ch = task & 3;
            cp16(base + row * ROWB + ch * 16,
                 g_Ah + (size_t)(m0 + row) * KDIM + kt + ch * 8);
        }
        #pragma unroll
        for (int i = 0; i < (BN * 4) / 256; ++i) {          // B: BN*4 chunks
            const int task = tid + i * 256;
            const int row = task >> 2, ch = task & 3;
            cp16(base + 128 * ROWB + row * ROWB + ch * 16,
                 g_Wf + (size_t)row * KDIM + kt + ch * 8);
        }
        CP_COMMIT();
    };

    load_stage(0, 0);
    load_stage(1, BK);

    for (int it = 0; it < NK; ++it) {
        if (it < NK - 1) { CP_WAIT(1); } else { CP_WAIT(0); }
        __syncthreads();
        if (it + 2 < NK) load_stage((it + 2) % 3, (it + 2) * BK);

        const uint32_t sA = smb + (it % 3) * STAGE;
        const uint32_t sB = sA + 128 * ROWB;
        #pragma unroll
        for (int kk = 0; kk < BK; kk += 16) {
            uint32_t a[4][4];
            #pragma unroll
            for (int i = 0; i < 4; ++i)
                ldsm4(a[i][0], a[i][1], a[i][2], a[i][3],
                      sA + a_base + i * (16 * ROWB) + kk * 2);
            uint32_t b[JT][2];
            #pragma unroll
            for (int jc = 0; jc < JT / 2; ++jc)
                ldsm4(b[2 * jc][0], b[2 * jc][1], b[2 * jc + 1][0], b[2 * jc + 1][1],
                      sB + b_base + jc * (16 * ROWB) + kk * 2);
            #pragma unroll
            for (int i = 0; i < 4; ++i)
                #pragma unroll
                for (int j = 0; j < JT; ++j)
                    mma_f16(c[i][j], a[i][0], a[i][1], a[i][2], a[i][3], b[j][0], b[j][1]);
        }
    }

    // epilogue
    #pragma unroll
    for (int i = 0; i < 4; ++i) {
        const int r0 = m0 + wm * 64 + i * 16 + g;
        #pragma unroll
        for (int j = 0; j < JT; ++j) {
            const int col = wn * (JT * 8) + j * 8 + 2 * t;
            if (col < Nout) {
                float b0 = bias[col];
                float b1 = (col + 1 < Nout) ? bias[col + 1] : 0.f;
                float v00 = c[i][j].x + b0, v01 = c[i][j].y + b1;
                float v10 = c[i][j].z + b0, v11 = c[i][j].w + b1;
                if (relu) {
                    v00 = fmaxf(v00, 0.f); v01 = fmaxf(v01, 0.f);
                    v10 = fmaxf(v10, 0.f); v11 = fmaxf(v11, 0.f);
                }
                if (HALF_OUT) {
                    __half* o = (__half*)outp;
                    __half2 h0 = __floats2half2_rn(v00, v01);
                    __half2 h1 = __floats2half2_rn(v10, v11);
                    *reinterpret_cast<__half2*>(o + (size_t)r0 * Nout + col) = h0;
                    *reinterpret_cast<__half2*>(o + (size_t)(r0 + 8) * Nout + col) = h1;
                } else {
                    float* o = (float*)outp;
                    const bool c1ok = (col + 1 < Nout);
                    if (!predM || r0 < N_NODES) {
                        o[(size_t)r0 * Nout + col] = v00;
                        if (c1ok) o[(size_t)r0 * Nout + col + 1] = v01;
                    }
                    if (!predM || r0 + 8 < N_NODES) {
                        o[(size_t)(r0 + 8) * Nout + col] = v10;
                        if (c1ok) o[(size_t)(r0 + 8) * Nout + col + 1] = v11;
                    }
                }
            }
        }
    }
}

// ---------------- launch ------------------------------------------------------
extern "C" void kernel_launch(void* const* d_in, const int* in_sizes, int n_in,
                              void* d_out, int out_size) {
    const float* x      = (const float*)d_in[0];
    const int*   esrc   = (const int*)  d_in[1];
    const int*   edst   = (const int*)  d_in[2];
    const int*   etyp   = (const int*)  d_in[3];
    const float* bases0 = (const float*)d_in[4];
    const float* comp0  = (const float*)d_in[5];
    const float* root0  = (const float*)d_in[6];
    const float* bias0  = (const float*)d_in[7];
    const float* bases1 = (const float*)d_in[8];
    const float* comp1  = (const float*)d_in[9];
    const float* root1  = (const float*)d_in[10];
    const float* bias1  = (const float*)d_in[11];
    const float* bases2 = (const float*)d_in[12];
    const float* comp2  = (const float*)d_in[13];
    const float* root2  = (const float*)d_in[14];
    const float* bias2  = (const float*)d_in[15];
    float* out = (float*)d_out;
    const int E = in_sizes[1];

    void* p;
    cudaGetSymbolAddress(&p, g_hx); __half* hx = (__half*)p;
    cudaGetSymbolAddress(&p, g_h0); __half* h0 = (__half*)p;
    cudaGetSymbolAddress(&p, g_h1); __half* h1 = (__half*)p;

    const int smem128 = 3 * (128 + 128) * 80;   // 61440
    const int smem64  = 3 * (128 + 64) * 80;    // 46080
    cudaFuncSetAttribute(k_gemm<128, 1>, cudaFuncAttributeMaxDynamicSharedMemorySize, smem128);
    cudaFuncSetAttribute(k_gemm<64, 0>,  cudaFuncAttributeMaxDynamicSharedMemorySize, smem64);

    // CSR by dst (reused by all 3 layers)
    k_zero_cnt<<<(N_NODES + 511) / 512, 512>>>();
    k_count  <<<(E + 255) / 256, 256>>>(edst, E);
    k_scan   <<<1, 1024>>>();
    k_scatter<<<(E + 255) / 256, 256>>>(esrc, edst, etyp, E);

    k_x2h<<<(N_NODES * (D / 2) + 255) / 256, 256>>>(x);

    const int wgrid = (128 * KDIM + 255) / 256;   // 576
    const int ggrid = N_PAD / 128;                // 782

    // layer 0
    k_make_w<<<wgrid, 256>>>(bases0, root0, D);
    k_pull  <<<2048, 256>>>(hx, comp0);
    k_gemm<128, 1><<<ggrid, 256, smem128>>>(bias0, h0, D, 1, 0);

    // layer 1
    k_make_w<<<wgrid, 256>>>(bases1, root1, D);
    k_pull  <<<2048, 256>>>(h0, comp1);
    k_gemm<128, 1><<<ggrid, 256, smem128>>>(bias1, h1, D, 1, 0);

    // layer 2 (d_out = 40)
    k_make_w<<<wgrid, 256>>>(bases2, root2, 40);
    k_pull  <<<2048, 256>>>(h1, comp2);
    k_gemm<64, 0><<<ggrid, 256, smem64>>>(bias2, out, 40, 0, 1);
}